// round 1
// baseline (speedup 1.0000x reference)
#include <cuda_runtime.h>
#include <cuda_bf16.h>

// CapsuleLayer dynamic routing, GB300.
// Shapes: x[B=128][R=1152][Ci=8], W[C=10][R=1152][Ci=8][O=16], 3 iterations.
// out v: [C][B][1][1][O] = 20480 fp32.
//
// Algebra: logits_t[c,b,r,o] = u[c,b,r,o] * A_t[c,b,o], A_t = sum of previous v's.
// Per iteration: E[c,b,o] = sum_r exp(u*A), S = sum_r u*exp(u*A), s = S/E.
// Squash uses GLOBAL Frobenius norm: scale = sqrt(n2)/(1+n2), v = scale*s.

#define BB 128
#define RR 1152
#define CI 8
#define CC 10
#define OO 16
#define U_ELEMS (CC * BB * RR * OO)   // 23,592,960 floats (~94.4 MB)
#define S_ELEMS (CC * BB * OO)        // 20,480

__device__ float g_u[U_ELEMS];
__device__ float g_s[S_ELEMS];
__device__ float g_A[S_ELEMS];

// ---------------------------------------------------------------------------
// Zero A (must run every launch for graph-replay determinism)
// ---------------------------------------------------------------------------
__global__ void init_kernel() {
    int i = blockIdx.x * blockDim.x + threadIdx.x;
    if (i < S_ELEMS) g_A[i] = 0.0f;
}

// ---------------------------------------------------------------------------
// GEMM: u[c][b][r][o] = sum_i x[b][r][i] * W[c][r][i][o]
// grid (36 r-chunks, 10 c), 256 threads.
// Thread = (r in 0..31, og in 0..7; owns o0=2*og, o0+1). W held in 16 regs.
// x staged per 32-b tile in smem (conflict-free reads, see analysis).
// ---------------------------------------------------------------------------
#define RB 32   // r rows per block
#define BT 32   // b tile

__global__ __launch_bounds__(256, 4)
void gemm_kernel(const float* __restrict__ x, const float* __restrict__ W) {
    const int c     = blockIdx.y;
    const int rbase = blockIdx.x * RB;
    const int tid   = threadIdx.x;
    const int r     = tid >> 3;        // 0..31
    const int og    = tid & 7;
    const int o0    = og * 2;

    // Load this thread's W slice into registers: W[c][rbase+r][i][o0..o0+1]
    float w0[CI], w1[CI];
    {
        const float* Wp = W + ((size_t)c * RR + rbase + r) * (CI * OO) + o0;
        #pragma unroll
        for (int i = 0; i < CI; i++) {
            w0[i] = Wp[i * OO];
            w1[i] = Wp[i * OO + 1];
        }
    }

    __shared__ float xs[BT][RB * CI];   // [b][r*8+i], 32 KB

    for (int bt = 0; bt < BB; bt += BT) {
        __syncthreads();
        // cooperative load of x[bt..bt+31][rbase..rbase+31][0..7] (8192 floats)
        for (int v = tid; v < BT * RB * CI / 4; v += 256) {
            int b = v >> 6;            // 64 float4 per b
            int q = v & 63;
            const float4* src = (const float4*)(x + ((size_t)(bt + b) * RR + rbase) * CI);
            ((float4*)xs[b])[q] = src[q];
        }
        __syncthreads();

        #pragma unroll 4
        for (int b = 0; b < BT; b++) {
            float4 xa = *(const float4*)&xs[b][r * CI];
            float4 xb = *(const float4*)&xs[b][r * CI + 4];
            float acc0, acc1;
            acc0 = xa.x * w0[0];
            acc1 = xa.x * w1[0];
            acc0 = fmaf(xa.y, w0[1], acc0);  acc1 = fmaf(xa.y, w1[1], acc1);
            acc0 = fmaf(xa.z, w0[2], acc0);  acc1 = fmaf(xa.z, w1[2], acc1);
            acc0 = fmaf(xa.w, w0[3], acc0);  acc1 = fmaf(xa.w, w1[3], acc1);
            acc0 = fmaf(xb.x, w0[4], acc0);  acc1 = fmaf(xb.x, w1[4], acc1);
            acc0 = fmaf(xb.y, w0[5], acc0);  acc1 = fmaf(xb.y, w1[5], acc1);
            acc0 = fmaf(xb.z, w0[6], acc0);  acc1 = fmaf(xb.z, w1[6], acc1);
            acc0 = fmaf(xb.w, w0[7], acc0);  acc1 = fmaf(xb.w, w1[7], acc1);

            size_t uidx = (((size_t)c * BB + bt + b) * RR + rbase + r) * OO + o0;
            float2 res = make_float2(acc0, acc1);
            *(float2*)&g_u[uidx] = res;
        }
    }
}

// ---------------------------------------------------------------------------
// Routing iteration: for each (c,b,o): E = sum_r exp(u*A), S = sum_r u*exp(u*A)
// s = S / E.   grid 1280 = (c*128+b), 256 threads = 16 r-groups x 16 o.
// Warp load pattern: 128 B contiguous per warp per step.
// ---------------------------------------------------------------------------
__global__ __launch_bounds__(256, 8)
void iter_kernel() {
    const int blk = blockIdx.x;                 // c*128 + b
    const float* __restrict__ ub = g_u + (size_t)blk * (RR * OO);
    const int tid = threadIdx.x;
    const int o   = tid & 15;
    const int rg  = tid >> 4;                    // 0..15

    const float a = g_A[blk * OO + o];

    float E = 0.0f, S = 0.0f;
    #pragma unroll 8
    for (int r = rg; r < RR; r += 16) {
        float uv = __ldg(&ub[r * OO + o]);
        float e  = __expf(uv * a);
        E += e;
        S = fmaf(e, uv, S);
    }

    __shared__ float sE[256], sS[256];
    sE[tid] = E; sS[tid] = S;
    __syncthreads();
    #pragma unroll
    for (int stride = 128; stride >= 16; stride >>= 1) {
        if (tid < stride) {
            sE[tid] += sE[tid + stride];
            sS[tid] += sS[tid + stride];
        }
        __syncthreads();
    }
    if (tid < 16) {
        g_s[blk * OO + tid] = sS[tid] / sE[tid];
    }
}

// ---------------------------------------------------------------------------
// Global squash + logits-accumulator update. One block, 1024 threads.
// n2 = sum over all 20480 of s^2; scale = sqrt(n2)/(1+n2); v = scale*s;
// A += v; optionally write v to out (final iteration).
// ---------------------------------------------------------------------------
__global__ __launch_bounds__(1024, 1)
void squash_kernel(float* __restrict__ out) {
    const int tid = threadIdx.x;

    float acc = 0.0f;
    for (int i = tid; i < S_ELEMS; i += 1024) {
        float v = g_s[i];
        acc = fmaf(v, v, acc);
    }
    // warp reduce
    #pragma unroll
    for (int off = 16; off; off >>= 1)
        acc += __shfl_xor_sync(0xffffffffu, acc, off);

    __shared__ float wred[32];
    __shared__ float s_n2;
    if ((tid & 31) == 0) wred[tid >> 5] = acc;
    __syncthreads();
    if (tid < 32) {
        float a2 = wred[tid];
        #pragma unroll
        for (int off = 16; off; off >>= 1)
            a2 += __shfl_xor_sync(0xffffffffu, a2, off);
        if (tid == 0) s_n2 = a2;
    }
    __syncthreads();

    const float n2 = s_n2;
    const float sc = sqrtf(n2) / (1.0f + n2);

    for (int i = tid; i < S_ELEMS; i += 1024) {
        float v = sc * g_s[i];
        g_A[i] += v;
        if (out) out[i] = v;
    }
}

// ---------------------------------------------------------------------------
extern "C" void kernel_launch(void* const* d_in, const int* in_sizes, int n_in,
                              void* d_out, int out_size) {
    const float* x = (const float*)d_in[0];   // [128][1152][8]
    const float* W = (const float*)d_in[1];   // [10][1152][8][16]
    // d_in[2] = num_iterations (always 3 per setup_inputs)
    float* out = (float*)d_out;               // [10][128][1][1][16]

    init_kernel<<<(S_ELEMS + 1023) / 1024, 1024>>>();
    gemm_kernel<<<dim3(RR / RB, CC), 256>>>(x, W);

    for (int it = 0; it < 3; it++) {
        iter_kernel<<<CC * BB, 256>>>();
        squash_kernel<<<1, 1024>>>(it == 2 ? out : nullptr);
    }
}

// round 2
// speedup vs baseline: 1.4431x; 1.4431x over previous
#include <cuda_runtime.h>
#include <cuda_bf16.h>

// CapsuleLayer dynamic routing, GB300 (sm_103a).
// x[B=128][R=1152][Ci=8], W[C=10][R=1152][Ci=8][O=16], 3 routing iterations.
// out v: [C][B][1][1][O] = 20480 fp32.
//
// Algebra: logits_t[c,b,r,o] = u[c,b,r,o] * A_t[c,b,o], where A_t = sum of
// previous v's (v broadcast over r). Per iteration, per (c,b,o):
//   E = sum_r exp(u*A), S = sum_r u*exp(u*A), s = S/E.
// Squash uses the GLOBAL Frobenius norm of s: scale = sqrt(n2)/(1+n2), v = scale*s.
// The norm reduction is fused into iter_kernel via one atomicAdd per block;
// the scale application/A update is fused into the NEXT iteration's prologue.

#define BB 128
#define RR 1152
#define CI 8
#define CC 10
#define OO 16
#define U_ELEMS (CC * BB * RR * OO)   // 23,592,960 floats (~94.4 MB)
#define S_ELEMS (CC * BB * OO)        // 20,480

__device__ float g_u[U_ELEMS];
__device__ float g_s[S_ELEMS];
__device__ float g_A[S_ELEMS];
__device__ float g_n2[4];

// ---------------------------------------------------------------------------
// GEMM: u[c][b][r][o] = sum_i x[b][r][i] * W[c][r][i][o]
// grid (36 r-chunks, 10 c), 256 threads. Thread = (r 0..31, og 0..7),
// owns o0=2*og, o0+1. W held in 16 regs; x staged per 32-b tile in smem.
// Also zeroes g_n2 (no concurrent reader; read only by later kernels).
// ---------------------------------------------------------------------------
#define RB 32   // r rows per block
#define BT 32   // b tile

__global__ __launch_bounds__(256, 4)
void gemm_kernel(const float* __restrict__ x, const float* __restrict__ W) {
    const int c     = blockIdx.y;
    const int rbase = blockIdx.x * RB;
    const int tid   = threadIdx.x;
    const int r     = tid >> 3;        // 0..31
    const int og    = tid & 7;
    const int o0    = og * 2;

    if (blockIdx.x == 0 && blockIdx.y == 0 && tid < 4) g_n2[tid] = 0.0f;

    // W[c][rbase+r][i][o0..o0+1] -> registers
    float w0[CI], w1[CI];
    {
        const float* Wp = W + ((size_t)c * RR + rbase + r) * (CI * OO) + o0;
        #pragma unroll
        for (int i = 0; i < CI; i++) {
            w0[i] = Wp[i * OO];
            w1[i] = Wp[i * OO + 1];
        }
    }

    __shared__ float xs[BT][RB * CI];   // 32 KB

    for (int bt = 0; bt < BB; bt += BT) {
        __syncthreads();
        for (int v = tid; v < BT * RB * CI / 4; v += 256) {
            int b = v >> 6;            // 64 float4 per b
            int q = v & 63;
            const float4* src = (const float4*)(x + ((size_t)(bt + b) * RR + rbase) * CI);
            ((float4*)xs[b])[q] = src[q];
        }
        __syncthreads();

        #pragma unroll 4
        for (int b = 0; b < BT; b++) {
            float4 xa = *(const float4*)&xs[b][r * CI];
            float4 xb = *(const float4*)&xs[b][r * CI + 4];
            float acc0, acc1;
            acc0 = xa.x * w0[0];
            acc1 = xa.x * w1[0];
            acc0 = fmaf(xa.y, w0[1], acc0);  acc1 = fmaf(xa.y, w1[1], acc1);
            acc0 = fmaf(xa.z, w0[2], acc0);  acc1 = fmaf(xa.z, w1[2], acc1);
            acc0 = fmaf(xa.w, w0[3], acc0);  acc1 = fmaf(xa.w, w1[3], acc1);
            acc0 = fmaf(xb.x, w0[4], acc0);  acc1 = fmaf(xb.x, w1[4], acc1);
            acc0 = fmaf(xb.y, w0[5], acc0);  acc1 = fmaf(xb.y, w1[5], acc1);
            acc0 = fmaf(xb.z, w0[6], acc0);  acc1 = fmaf(xb.z, w1[6], acc1);
            acc0 = fmaf(xb.w, w0[7], acc0);  acc1 = fmaf(xb.w, w1[7], acc1);

            size_t uidx = (((size_t)c * BB + bt + b) * RR + rbase + r) * OO + o0;
            *(float2*)&g_u[uidx] = make_float2(acc0, acc1);
        }
    }
}

// ---------------------------------------------------------------------------
// Routing iteration t (t = 0,1,2).
// Prologue (threads 0..15): apply previous iteration's squash:
//   scale = sqrt(n2[t-1])/(1+n2[t-1]); v_prev = scale*s_prev;
//   a = (t==1 ? v_prev : g_A + v_prev); g_A updated at t==1 (only read at t==2).
// Main: per (c,b,o): E = sum_r exp(u*a), S = sum_r u*exp(u*a); s = S/E.
// Epilogue: write s; lane 0 atomicAdds sum(s^2) of this block into g_n2[t].
// grid 1280 = c*128+b, 256 threads = 64 r-groups x 4 o-groups (float4 loads).
// ---------------------------------------------------------------------------
__global__ __launch_bounds__(256, 8)
void iter_kernel(int t) {
    const int blk = blockIdx.x;                 // c*128 + b
    const int tid = threadIdx.x;
    const int og  = tid & 3;                    // o = og*4 + k
    const int rg  = tid >> 2;                   // 0..63
    const float* __restrict__ ub = g_u + (size_t)blk * (RR * OO);

    __shared__ float sA[16];
    __shared__ float pE[8][16], pS[8][16];

    if (tid < 16) {
        float a = 0.0f;
        if (t > 0) {
            float n2 = g_n2[t - 1];
            float sc = sqrtf(n2) / (1.0f + n2);
            float v  = sc * g_s[blk * OO + tid];
            if (t == 1) {
                a = v;
                g_A[blk * OO + tid] = a;
            } else {
                a = g_A[blk * OO + tid] + v;
            }
        }
        sA[tid] = a;
    }
    __syncthreads();

    const float a0 = sA[og * 4 + 0];
    const float a1 = sA[og * 4 + 1];
    const float a2 = sA[og * 4 + 2];
    const float a3 = sA[og * 4 + 3];

    float E0 = 0.f, E1 = 0.f, E2 = 0.f, E3 = 0.f;
    float S0 = 0.f, S1 = 0.f, S2 = 0.f, S3 = 0.f;

    #pragma unroll 6
    for (int r = rg; r < RR; r += 64) {        // 18 iterations
        float4 u4 = *(const float4*)&ub[r * OO + og * 4];
        float e0 = __expf(u4.x * a0); E0 += e0; S0 = fmaf(e0, u4.x, S0);
        float e1 = __expf(u4.y * a1); E1 += e1; S1 = fmaf(e1, u4.y, S1);
        float e2 = __expf(u4.z * a2); E2 += e2; S2 = fmaf(e2, u4.z, S2);
        float e3 = __expf(u4.w * a3); E3 += e3; S3 = fmaf(e3, u4.w, S3);
    }

    // Reduce over the 8 rg-values inside each warp (lane bits 2,3,4).
    #pragma unroll
    for (int off = 4; off <= 16; off <<= 1) {
        E0 += __shfl_xor_sync(0xffffffffu, E0, off);
        E1 += __shfl_xor_sync(0xffffffffu, E1, off);
        E2 += __shfl_xor_sync(0xffffffffu, E2, off);
        E3 += __shfl_xor_sync(0xffffffffu, E3, off);
        S0 += __shfl_xor_sync(0xffffffffu, S0, off);
        S1 += __shfl_xor_sync(0xffffffffu, S1, off);
        S2 += __shfl_xor_sync(0xffffffffu, S2, off);
        S3 += __shfl_xor_sync(0xffffffffu, S3, off);
    }
    const int warp = tid >> 5;
    const int lane = tid & 31;
    if (lane < 4) {
        *(float4*)&pE[warp][lane * 4] = make_float4(E0, E1, E2, E3);
        *(float4*)&pS[warp][lane * 4] = make_float4(S0, S1, S2, S3);
    }
    __syncthreads();

    if (tid < 16) {
        float E = 0.f, S = 0.f;
        #pragma unroll
        for (int w = 0; w < 8; w++) { E += pE[w][tid]; S += pS[w][tid]; }
        float s = S / E;
        g_s[blk * OO + tid] = s;

        float q = s * s;
        q += __shfl_xor_sync(0x0000ffffu, q, 1);
        q += __shfl_xor_sync(0x0000ffffu, q, 2);
        q += __shfl_xor_sync(0x0000ffffu, q, 4);
        q += __shfl_xor_sync(0x0000ffffu, q, 8);
        if (tid == 0) atomicAdd(&g_n2[t], q);
    }
}

// ---------------------------------------------------------------------------
// Final: out = scale(n2[2]) * s2. Wide grid, trivially fast.
// ---------------------------------------------------------------------------
__global__ __launch_bounds__(256)
void final_kernel(float* __restrict__ out) {
    int i = blockIdx.x * blockDim.x + threadIdx.x;
    if (i < S_ELEMS) {
        float n2 = g_n2[2];
        float sc = sqrtf(n2) / (1.0f + n2);
        out[i] = sc * g_s[i];
    }
}

// ---------------------------------------------------------------------------
extern "C" void kernel_launch(void* const* d_in, const int* in_sizes, int n_in,
                              void* d_out, int out_size) {
    const float* x = (const float*)d_in[0];   // [128][1152][8]
    const float* W = (const float*)d_in[1];   // [10][1152][8][16]
    float* out = (float*)d_out;               // [10][128][1][1][16]

    gemm_kernel<<<dim3(RR / RB, CC), 256>>>(x, W);
    iter_kernel<<<CC * BB, 256>>>(0);
    iter_kernel<<<CC * BB, 256>>>(1);
    iter_kernel<<<CC * BB, 256>>>(2);
    final_kernel<<<(S_ELEMS + 255) / 256, 256>>>(out);
}